// round 2
// baseline (speedup 1.0000x reference)
#include <cuda_runtime.h>

#define THREADS 256

// Chamfer distance, both directions fused into one launch via blockIdx.z.
//
// Correctness-critical: the distance is computed with the SAME fp32 rounding
// sequence as the JAX reference (|x|^2 + |y|^2 - 2 x.y expansion, cublas-style
// fma chain for the dot product), so that argmin matches bit-exactly even for
// near-tied candidates where the cancellation noise (~1e-6 abs) exceeds the
// true gap. No fma contraction is allowed on the squared-norm sums.
__global__ __launch_bounds__(THREADS, 1)
void chamfer_kernel(const float* __restrict__ xyz1,
                    const float* __restrict__ xyz2,
                    float* __restrict__ out,
                    int N, int M, int B) {
    extern __shared__ float4 sh[];
    const int dir = blockIdx.z;
    const int b   = blockIdx.y;

    const float* q;
    const float* c;
    int Nq, Nc;
    float* dist_out;
    float* idx_out;
    if (dir == 0) {
        // dist1/idx1: for each point of xyz1, nearest in xyz2
        q = xyz1; c = xyz2; Nq = N; Nc = M;
        dist_out = out;                                        // dist1
        idx_out  = out + (size_t)B * (N + M);                  // idx1
    } else {
        // dist2/idx2: for each point of xyz2, nearest in xyz1
        q = xyz2; c = xyz1; Nq = M; Nc = N;
        dist_out = out + (size_t)B * N;                        // dist2
        idx_out  = out + (size_t)B * (N + M) + (size_t)B * N;  // idx2
    }

    // ---- fill shared memory: (cx, cy, cz, |c|^2) with reference rounding ----
    const float* cb = c + (size_t)b * Nc * 3;
    for (int j = threadIdx.x; j < Nc; j += THREADS) {
        float x = cb[3 * j + 0];
        float y = cb[3 * j + 1];
        float z = cb[3 * j + 2];
        // (x*x + y*y) + z*z, each op individually rounded (no fma)
        float sq = __fadd_rn(__fadd_rn(__fmul_rn(x, x), __fmul_rn(y, y)),
                             __fmul_rn(z, z));
        sh[j] = make_float4(x, y, z, sq);
    }
    __syncthreads();

    const int i = blockIdx.x * THREADS + threadIdx.x;
    if (i >= Nq) return;

    const float* qp = q + ((size_t)b * Nq + i) * 3;
    const float ax = qp[0];
    const float ay = qp[1];
    const float az = qp[2];
    const float sqa = __fadd_rn(__fadd_rn(__fmul_rn(ax, ax), __fmul_rn(ay, ay)),
                                __fmul_rn(az, az));

    float best[8];
    int   bj[8];
#pragma unroll
    for (int k = 0; k < 8; k++) { best[k] = 3.402823466e38f; bj[k] = 0; }

    // Nc is a multiple of 8 here (8192).
    for (int j = 0; j < Nc; j += 8) {
#pragma unroll
        for (int k = 0; k < 8; k++) {
            float4 cc = sh[j + k];
            // cross = fma(az*cz, fma(ay*cy, ax*cx)) : cublas K-ascending chain
            float cross = fmaf(cc.z, az, fmaf(cc.y, ay, __fmul_rn(cc.x, ax)));
            // d = (sqa + sqc) - 2*cross ; 2*cross exact => fma(-2,cross,s) is
            // bit-identical to the reference's fsub(s, 2*cross).
            float s = __fadd_rn(sqa, cc.w);
            float e = fmaf(-2.0f, cross, s);
            if (e < best[k]) { best[k] = e; bj[k] = j; }
        }
    }

    // merge the 8 accumulators; exact ties -> smallest index (argmin semantics)
    float fb = best[0];
    int   ib = bj[0];
#pragma unroll
    for (int k = 1; k < 8; k++) {
        int ik = bj[k] + k;
        if (best[k] < fb || (best[k] == fb && ik < ib)) { fb = best[k]; ib = ik; }
    }

    dist_out[(size_t)b * Nq + i] = fb;
    idx_out [(size_t)b * Nq + i] = (float)ib;
}

extern "C" void kernel_launch(void* const* d_in, const int* in_sizes, int n_in,
                              void* d_out, int out_size) {
    const float* xyz1 = (const float*)d_in[0];
    const float* xyz2 = (const float*)d_in[1];
    float* out = (float*)d_out;

    const int B = 2;
    const int N = in_sizes[0] / (3 * B);
    const int M = in_sizes[1] / (3 * B);
    const int maxNM = (N > M) ? N : M;

    const size_t shmem = (size_t)maxNM * sizeof(float4);  // 128 KB for 8192
    cudaFuncSetAttribute(chamfer_kernel,
                         cudaFuncAttributeMaxDynamicSharedMemorySize,
                         (int)shmem);

    dim3 grid((maxNM + THREADS - 1) / THREADS, B, 2);
    chamfer_kernel<<<grid, THREADS, shmem>>>(xyz1, xyz2, out, N, M, B);
}

// round 3
// speedup vs baseline: 1.2185x; 1.2185x over previous
#include <cuda_runtime.h>
#include <cstdint>

#define THREADS 256

// Packed-fp32x2 helpers (sm_103a). Per-lane .rn rounding is bit-identical to
// scalar __fmul_rn / __fadd_rn / fmaf, which is what keeps the argmin
// bit-exact vs the JAX reference.
#define MUL2(d, a, b) \
    asm("mul.rn.f32x2 %0, %1, %2;" : "=l"(d) : "l"(a), "l"(b))
#define ADD2(d, a, b) \
    asm("add.rn.f32x2 %0, %1, %2;" : "=l"(d) : "l"(a), "l"(b))
#define FMA2(d, a, b, c) \
    asm("fma.rn.f32x2 %0, %1, %2, %3;" : "=l"(d) : "l"(a), "l"(b), "l"(c))

__device__ __forceinline__ unsigned long long pack2(float lo, float hi) {
    unsigned long long r;
    asm("mov.b64 %0, {%1, %2};" : "=l"(r) : "f"(lo), "f"(hi));
    return r;
}
__device__ __forceinline__ void unpack2(float& lo, float& hi,
                                        unsigned long long v) {
    asm("mov.b64 {%0, %1}, %2;" : "=f"(lo), "=f"(hi) : "l"(v));
}

// Chamfer distance, both directions fused via blockIdx.z.
// Candidates cached in smem in pair-SoA layout:
//   sh[2p]   = (x0, x1, y0, y1)
//   sh[2p+1] = (z0, z1, w0, w1)   w = |c|^2 with reference rounding
// so each LDS.128 register quad supplies two aligned f32x2 operands directly.
// Distance key per candidate uses the exact reference rounding sequence:
//   cross = fma(cz,az, fma(cy,ay, cx*ax)) ; e = fma(-2, cross, sqa + sqc)
__global__ __launch_bounds__(THREADS, 1)
void chamfer_kernel(const float* __restrict__ xyz1,
                    const float* __restrict__ xyz2,
                    float* __restrict__ out,
                    int N, int M, int B) {
    extern __shared__ float4 sh[];
    const int dir = blockIdx.z;
    const int b   = blockIdx.y;

    const float* q;
    const float* c;
    int Nq, Nc;
    float* dist_out;
    float* idx_out;
    if (dir == 0) {
        q = xyz1; c = xyz2; Nq = N; Nc = M;
        dist_out = out;                                        // dist1
        idx_out  = out + (size_t)B * (N + M);                  // idx1
    } else {
        q = xyz2; c = xyz1; Nq = M; Nc = N;
        dist_out = out + (size_t)B * N;                        // dist2
        idx_out  = out + (size_t)B * (N + M) + (size_t)B * N;  // idx2
    }

    // ---- fill shared memory (pair layout), reference rounding for |c|^2 ----
    const float* cb = c + (size_t)b * Nc * 3;
    const int npairs = Nc >> 1;  // Nc is even (8192)
    for (int p = threadIdx.x; p < npairs; p += THREADS) {
        float x0 = cb[6 * p + 0], y0 = cb[6 * p + 1], z0 = cb[6 * p + 2];
        float x1 = cb[6 * p + 3], y1 = cb[6 * p + 4], z1 = cb[6 * p + 5];
        float w0 = __fadd_rn(__fadd_rn(__fmul_rn(x0, x0), __fmul_rn(y0, y0)),
                             __fmul_rn(z0, z0));
        float w1 = __fadd_rn(__fadd_rn(__fmul_rn(x1, x1), __fmul_rn(y1, y1)),
                             __fmul_rn(z1, z1));
        sh[2 * p]     = make_float4(x0, x1, y0, y1);
        sh[2 * p + 1] = make_float4(z0, z1, w0, w1);
    }
    __syncthreads();

    // Interleaved query assignment: balanced across all gridDim.x CTAs.
    const int i = threadIdx.x * gridDim.x + blockIdx.x;
    if (i >= Nq) return;

    const float* qp = q + ((size_t)b * Nq + i) * 3;
    const float ax = qp[0];
    const float ay = qp[1];
    const float az = qp[2];
    const float sqa = __fadd_rn(__fadd_rn(__fmul_rn(ax, ax), __fmul_rn(ay, ay)),
                                __fmul_rn(az, az));

    const unsigned long long ax2   = pack2(ax, ax);
    const unsigned long long ay2   = pack2(ay, ay);
    const unsigned long long az2   = pack2(az, az);
    const unsigned long long sqa2  = pack2(sqa, sqa);
    const unsigned long long m2w2  = pack2(-2.0f, -2.0f);

    float best[8];
    int   bj[8];
#pragma unroll
    for (int k = 0; k < 8; k++) { best[k] = 3.402823466e38f; bj[k] = 0; }

    // Nc multiple of 8 (8192): 4 pairs (8 candidates) per iteration.
    for (int j = 0; j < Nc; j += 8) {
#pragma unroll
        for (int p = 0; p < 4; p++) {
            float4 A = sh[j + 2 * p];      // (x0,x1,y0,y1)
            float4 Bv = sh[j + 2 * p + 1]; // (z0,z1,w0,w1)
            unsigned long long x2 = pack2(A.x, A.y);
            unsigned long long y2 = pack2(A.z, A.w);
            unsigned long long z2 = pack2(Bv.x, Bv.y);
            unsigned long long w2 = pack2(Bv.z, Bv.w);
            unsigned long long c0, c1, c2, s2, e2;
            MUL2(c0, x2, ax2);        // cx*ax
            FMA2(c1, y2, ay2, c0);    // fma(cy,ay, .)
            FMA2(c2, z2, az2, c1);    // fma(cz,az, .)
            ADD2(s2, sqa2, w2);       // sqa + sqc
            FMA2(e2, m2w2, c2, s2);   // fma(-2, cross, s)
            float e0, e1;
            unpack2(e0, e1, e2);
            if (e0 < best[2 * p])     { best[2 * p]     = e0; bj[2 * p]     = j; }
            if (e1 < best[2 * p + 1]) { best[2 * p + 1] = e1; bj[2 * p + 1] = j; }
        }
    }

    // merge the 8 accumulators; exact ties -> smallest index
    float fb = best[0];
    int   ib = bj[0];
#pragma unroll
    for (int k = 1; k < 8; k++) {
        int ik = bj[k] + k;
        if (best[k] < fb || (best[k] == fb && ik < ib)) { fb = best[k]; ib = ik; }
    }

    dist_out[(size_t)b * Nq + i] = fb;
    idx_out [(size_t)b * Nq + i] = (float)ib;
}

extern "C" void kernel_launch(void* const* d_in, const int* in_sizes, int n_in,
                              void* d_out, int out_size) {
    const float* xyz1 = (const float*)d_in[0];
    const float* xyz2 = (const float*)d_in[1];
    float* out = (float*)d_out;

    const int B = 2;
    const int N = in_sizes[0] / (3 * B);
    const int M = in_sizes[1] / (3 * B);
    const int maxNM = (N > M) ? N : M;

    const size_t shmem = (size_t)maxNM * sizeof(float4);  // 128 KB for 8192
    cudaFuncSetAttribute(chamfer_kernel,
                         cudaFuncAttributeMaxDynamicSharedMemorySize,
                         (int)shmem);

    // grid.x chosen so total CTAs = 148 (one per SM): 37 * 2 * 2.
    // Queries are interleaved across CTAs, so load is balanced.
    const int gx = 37;
    dim3 grid(gx, B, 2);
    chamfer_kernel<<<grid, THREADS, shmem>>>(xyz1, xyz2, out, N, M, B);
}

// round 4
// speedup vs baseline: 1.3963x; 1.1459x over previous
#include <cuda_runtime.h>
#include <cstdint>

#define THREADS 512   // 2 chunk-threads per query lane (256 lanes)

// Packed-fp32x2 helpers (sm_103a). Per-lane .rn rounding is bit-identical to
// scalar ops, preserving argmin bit-exactness vs the JAX reference.
#define MUL2(d, a, b) \
    asm("mul.rn.f32x2 %0, %1, %2;" : "=l"(d) : "l"(a), "l"(b))
#define ADD2(d, a, b) \
    asm("add.rn.f32x2 %0, %1, %2;" : "=l"(d) : "l"(a), "l"(b))
#define FMA2(d, a, b, c) \
    asm("fma.rn.f32x2 %0, %1, %2, %3;" : "=l"(d) : "l"(a), "l"(b), "l"(c))

__device__ __forceinline__ unsigned long long pack2(float lo, float hi) {
    unsigned long long r;
    asm("mov.b64 %0, {%1, %2};" : "=l"(r) : "f"(lo), "f"(hi));
    return r;
}
__device__ __forceinline__ void unpack2(float& lo, float& hi,
                                        unsigned long long v) {
    asm("mov.b64 {%0, %1}, %2;" : "=f"(lo), "=f"(hi) : "l"(v));
}

// Chamfer distance, both directions fused via blockIdx.z.
// Candidates cached in smem in pair-SoA layout:
//   sh[2p]   = (x0, x1, y0, y1)
//   sh[2p+1] = (z0, z1, w0, w1)   w = |c|^2 with reference rounding
// Each query lane is scanned by 2 threads over disjoint candidate halves;
// partials merged through static smem.
// Hot loop: per 8-candidate block, FMNMX tree -> one (best, blockbase) update.
// Exact index recovered post-loop by rescanning only the winning block.
__global__ __launch_bounds__(THREADS, 1)
void chamfer_kernel(const float* __restrict__ xyz1,
                    const float* __restrict__ xyz2,
                    float* __restrict__ out,
                    int N, int M, int B) {
    extern __shared__ float4 sh[];
    __shared__ float2 red[THREADS];  // (best, idx_as_float) per thread

    const int dir = blockIdx.z;
    const int b   = blockIdx.y;

    const float* q;
    const float* c;
    int Nq, Nc;
    float* dist_out;
    float* idx_out;
    if (dir == 0) {
        q = xyz1; c = xyz2; Nq = N; Nc = M;
        dist_out = out;                                        // dist1
        idx_out  = out + (size_t)B * (N + M);                  // idx1
    } else {
        q = xyz2; c = xyz1; Nq = M; Nc = N;
        dist_out = out + (size_t)B * N;                        // dist2
        idx_out  = out + (size_t)B * (N + M) + (size_t)B * N;  // idx2
    }

    // ---- fill shared memory (pair layout), reference rounding for |c|^2 ----
    const float* cb = c + (size_t)b * Nc * 3;
    const int npairs = Nc >> 1;
    for (int p = threadIdx.x; p < npairs; p += THREADS) {
        float x0 = cb[6 * p + 0], y0 = cb[6 * p + 1], z0 = cb[6 * p + 2];
        float x1 = cb[6 * p + 3], y1 = cb[6 * p + 4], z1 = cb[6 * p + 5];
        float w0 = __fadd_rn(__fadd_rn(__fmul_rn(x0, x0), __fmul_rn(y0, y0)),
                             __fmul_rn(z0, z0));
        float w1 = __fadd_rn(__fadd_rn(__fmul_rn(x1, x1), __fmul_rn(y1, y1)),
                             __fmul_rn(z1, z1));
        sh[2 * p]     = make_float4(x0, x1, y0, y1);
        sh[2 * p + 1] = make_float4(z0, z1, w0, w1);
    }
    __syncthreads();

    const int qlane = threadIdx.x & 255;
    const int chunk = threadIdx.x >> 8;       // 0 or 1
    const int i = qlane * gridDim.x + blockIdx.x;   // interleaved, balanced
    const bool valid = (i < Nq);
    const int iq = valid ? i : 0;             // clamp to avoid OOB; no divergence

    const float* qp = q + ((size_t)b * Nq + iq) * 3;
    const float ax = qp[0];
    const float ay = qp[1];
    const float az = qp[2];
    const float sqa = __fadd_rn(__fadd_rn(__fmul_rn(ax, ax), __fmul_rn(ay, ay)),
                                __fmul_rn(az, az));

    const unsigned long long ax2  = pack2(ax, ax);
    const unsigned long long ay2  = pack2(ay, ay);
    const unsigned long long az2  = pack2(az, az);
    const unsigned long long sqa2 = pack2(sqa, sqa);
    const unsigned long long m22  = pack2(-2.0f, -2.0f);

    const int half = Nc >> 1;
    const int cbase = chunk * half;

    float best = 3.402823466e38f;
    int   bj   = cbase;

    for (int j = cbase; j < cbase + half; j += 8) {
        float e[8];
#pragma unroll
        for (int p = 0; p < 4; p++) {
            float4 A  = sh[j + 2 * p];      // (x0,x1,y0,y1)
            float4 Bv = sh[j + 2 * p + 1];  // (z0,z1,w0,w1)
            unsigned long long x2 = pack2(A.x, A.y);
            unsigned long long y2 = pack2(A.z, A.w);
            unsigned long long z2 = pack2(Bv.x, Bv.y);
            unsigned long long w2 = pack2(Bv.z, Bv.w);
            unsigned long long c0, c1, c2, s2, e2;
            MUL2(c0, x2, ax2);
            FMA2(c1, y2, ay2, c0);
            FMA2(c2, z2, az2, c1);
            ADD2(s2, sqa2, w2);
            FMA2(e2, m22, c2, s2);
            unpack2(e[2 * p], e[2 * p + 1], e2);
        }
        // 7-op min tree over the 8-candidate block
        float m01 = fminf(e[0], e[1]);
        float m23 = fminf(e[2], e[3]);
        float m45 = fminf(e[4], e[5]);
        float m67 = fminf(e[6], e[7]);
        float m03 = fminf(m01, m23);
        float m47 = fminf(m45, m67);
        float bm  = fminf(m03, m47);
        if (bm < best) bj = j;          // strict < : earliest block wins ties
        best = fminf(best, bm);
    }

    // ---- recover index within the winning block (first occurrence) ----
    int kwin = 0;
#pragma unroll
    for (int k = 7; k >= 0; k--) {
        int p = k >> 1, lane = k & 1;
        float4 A  = sh[bj + 2 * p];
        float4 Bv = sh[bj + 2 * p + 1];
        float cx = lane ? A.y  : A.x;
        float cy = lane ? A.w  : A.z;
        float cz = lane ? Bv.y : Bv.x;
        float cw = lane ? Bv.w : Bv.z;
        float cross = fmaf(cz, az, fmaf(cy, ay, __fmul_rn(cx, ax)));
        float ek = fmaf(-2.0f, cross, __fadd_rn(sqa, cw));
        if (ek == best) kwin = k;       // descending k: smallest k survives
    }

    red[threadIdx.x] = make_float2(best, (float)(bj + kwin));
    __syncthreads();

    // ---- merge the two candidate-halves; chunk0 wins ties (smaller index) --
    if (threadIdx.x < 256 && valid) {
        float2 r0 = red[threadIdx.x];
        float2 r1 = red[threadIdx.x + 256];
        float fb; float fi;
        if (r1.x < r0.x) { fb = r1.x; fi = r1.y; }
        else             { fb = r0.x; fi = r0.y; }
        dist_out[(size_t)b * Nq + i] = fb;
        idx_out [(size_t)b * Nq + i] = fi;
    }
}

extern "C" void kernel_launch(void* const* d_in, const int* in_sizes, int n_in,
                              void* d_out, int out_size) {
    const float* xyz1 = (const float*)d_in[0];
    const float* xyz2 = (const float*)d_in[1];
    float* out = (float*)d_out;

    const int B = 2;
    const int N = in_sizes[0] / (3 * B);
    const int M = in_sizes[1] / (3 * B);
    const int maxNM = (N > M) ? N : M;

    const size_t shmem = (size_t)maxNM * sizeof(float4);  // 128 KB for 8192
    cudaFuncSetAttribute(chamfer_kernel,
                         cudaFuncAttributeMaxDynamicSharedMemorySize,
                         (int)shmem);

    // 37 * 2 * 2 = 148 CTAs: one per SM, queries interleaved for balance.
    dim3 grid(37, B, 2);
    chamfer_kernel<<<grid, THREADS, shmem>>>(xyz1, xyz2, out, N, M, B);
}

// round 5
// speedup vs baseline: 1.6963x; 1.2149x over previous
#include <cuda_runtime.h>
#include <cstdint>

#define THREADS 512   // 128 query-pairs x 4 candidate chunks
#define NCHUNK  4

// Packed-fp32x2 helpers (sm_103a). Per-lane .rn rounding is bit-identical to
// scalar ops, preserving argmin bit-exactness vs the JAX reference.
#define MUL2(d, a, b) \
    asm("mul.rn.f32x2 %0, %1, %2;" : "=l"(d) : "l"(a), "l"(b))
#define ADD2(d, a, b) \
    asm("add.rn.f32x2 %0, %1, %2;" : "=l"(d) : "l"(a), "l"(b))
#define FMA2(d, a, b, c) \
    asm("fma.rn.f32x2 %0, %1, %2, %3;" : "=l"(d) : "l"(a), "l"(b), "l"(c))

__device__ __forceinline__ unsigned long long pack2(float lo, float hi) {
    unsigned long long r;
    asm("mov.b64 %0, {%1, %2};" : "=l"(r) : "f"(lo), "f"(hi));
    return r;
}
__device__ __forceinline__ void unpack2(float& lo, float& hi,
                                        unsigned long long v) {
    asm("mov.b64 {%0, %1}, %2;" : "=f"(lo), "=f"(hi) : "l"(v));
}

// Chamfer distance, both directions fused via blockIdx.z.
// Candidates cached in smem in pair-SoA layout:
//   sh[2p]   = (x0, x1, y0, y1)
//   sh[2p+1] = (z0, z1, w0, w1)   w = |c|^2 with reference rounding
// Each thread owns TWO queries and scans one of 4 candidate chunks (2048
// candidates), so every LDS.128 is amortized over 2 distance evals.
// Hot loop: per 8-candidate block per query, FMNMX tree -> one (best, base)
// update; exact winning index recovered post-loop by rescanning one block.
__global__ __launch_bounds__(THREADS, 1)
void chamfer_kernel(const float* __restrict__ xyz1,
                    const float* __restrict__ xyz2,
                    float* __restrict__ out,
                    int N, int M, int B) {
    extern __shared__ float4 sh[];
    __shared__ float2 red[2][THREADS];   // per-query-slot (best, idx) partials

    const int dir = blockIdx.z;
    const int b   = blockIdx.y;

    const float* q;
    const float* c;
    int Nq, Nc;
    float* dist_out;
    float* idx_out;
    if (dir == 0) {
        q = xyz1; c = xyz2; Nq = N; Nc = M;
        dist_out = out;                                        // dist1
        idx_out  = out + (size_t)B * (N + M);                  // idx1
    } else {
        q = xyz2; c = xyz1; Nq = M; Nc = N;
        dist_out = out + (size_t)B * N;                        // dist2
        idx_out  = out + (size_t)B * (N + M) + (size_t)B * N;  // idx2
    }

    // ---- fill shared memory (pair layout), reference rounding for |c|^2 ----
    const float* cb = c + (size_t)b * Nc * 3;
    const int npairs = Nc >> 1;
    for (int p = threadIdx.x; p < npairs; p += THREADS) {
        float x0 = cb[6 * p + 0], y0 = cb[6 * p + 1], z0 = cb[6 * p + 2];
        float x1 = cb[6 * p + 3], y1 = cb[6 * p + 4], z1 = cb[6 * p + 5];
        float w0 = __fadd_rn(__fadd_rn(__fmul_rn(x0, x0), __fmul_rn(y0, y0)),
                             __fmul_rn(z0, z0));
        float w1 = __fadd_rn(__fadd_rn(__fmul_rn(x1, x1), __fmul_rn(y1, y1)),
                             __fmul_rn(z1, z1));
        sh[2 * p]     = make_float4(x0, x1, y0, y1);
        sh[2 * p + 1] = make_float4(z0, z1, w0, w1);
    }
    __syncthreads();

    const int qpair = threadIdx.x & 127;   // which query pair
    const int chunk = threadIdx.x >> 7;    // candidate chunk 0..3

    // two query lanes for this thread (interleaved across CTAs for balance)
    const int l0 = 2 * qpair;
    const int l1 = 2 * qpair + 1;
    const int i0 = l0 * gridDim.x + blockIdx.x;
    const int i1 = l1 * gridDim.x + blockIdx.x;
    const int iq0 = (i0 < Nq) ? i0 : 0;
    const int iq1 = (i1 < Nq) ? i1 : 0;

    const float* qp0 = q + ((size_t)b * Nq + iq0) * 3;
    const float* qp1 = q + ((size_t)b * Nq + iq1) * 3;
    const float ax0 = qp0[0], ay0 = qp0[1], az0 = qp0[2];
    const float ax1 = qp1[0], ay1 = qp1[1], az1 = qp1[2];
    const float sq0 = __fadd_rn(__fadd_rn(__fmul_rn(ax0, ax0), __fmul_rn(ay0, ay0)),
                                __fmul_rn(az0, az0));
    const float sq1 = __fadd_rn(__fadd_rn(__fmul_rn(ax1, ax1), __fmul_rn(ay1, ay1)),
                                __fmul_rn(az1, az1));

    const unsigned long long AX0 = pack2(ax0, ax0), AY0 = pack2(ay0, ay0);
    const unsigned long long AZ0 = pack2(az0, az0), SQ0 = pack2(sq0, sq0);
    const unsigned long long AX1 = pack2(ax1, ax1), AY1 = pack2(ay1, ay1);
    const unsigned long long AZ1 = pack2(az1, az1), SQ1 = pack2(sq1, sq1);
    const unsigned long long M22 = pack2(-2.0f, -2.0f);

    const int csz   = Nc / NCHUNK;         // 2048
    const int cbase = chunk * csz;

    float best0 = 3.402823466e38f, best1 = 3.402823466e38f;
    int   bj0 = cbase, bj1 = cbase;

    for (int j = cbase; j < cbase + csz; j += 8) {
        float e0[8], e1[8];
#pragma unroll
        for (int p = 0; p < 4; p++) {
            float4 A  = sh[j + 2 * p];      // (x0,x1,y0,y1)
            float4 Bv = sh[j + 2 * p + 1];  // (z0,z1,w0,w1)
            unsigned long long x2 = pack2(A.x, A.y);
            unsigned long long y2 = pack2(A.z, A.w);
            unsigned long long z2 = pack2(Bv.x, Bv.y);
            unsigned long long w2 = pack2(Bv.z, Bv.w);
            unsigned long long t0, t1, t2, s2, r2;
            // query 0
            MUL2(t0, x2, AX0);
            FMA2(t1, y2, AY0, t0);
            FMA2(t2, z2, AZ0, t1);
            ADD2(s2, SQ0, w2);
            FMA2(r2, M22, t2, s2);
            unpack2(e0[2 * p], e0[2 * p + 1], r2);
            // query 1 (same candidate registers)
            MUL2(t0, x2, AX1);
            FMA2(t1, y2, AY1, t0);
            FMA2(t2, z2, AZ1, t1);
            ADD2(s2, SQ1, w2);
            FMA2(r2, M22, t2, s2);
            unpack2(e1[2 * p], e1[2 * p + 1], r2);
        }
        // 7-op min trees (alu pipe)
        float a01 = fminf(e0[0], e0[1]), a23 = fminf(e0[2], e0[3]);
        float a45 = fminf(e0[4], e0[5]), a67 = fminf(e0[6], e0[7]);
        float a03 = fminf(a01, a23),     a47 = fminf(a45, a67);
        float bm0 = fminf(a03, a47);
        float b01 = fminf(e1[0], e1[1]), b23 = fminf(e1[2], e1[3]);
        float b45 = fminf(e1[4], e1[5]), b67 = fminf(e1[6], e1[7]);
        float b03 = fminf(b01, b23),     b47 = fminf(b45, b67);
        float bm1 = fminf(b03, b47);
        if (bm0 < best0) bj0 = j;       // strict < : earliest block wins ties
        best0 = fminf(best0, bm0);
        if (bm1 < best1) bj1 = j;
        best1 = fminf(best1, bm1);
    }

    // ---- recover index within the winning block (first occurrence) ----
    int kw0 = 0, kw1 = 0;
#pragma unroll
    for (int k = 7; k >= 0; k--) {
        int p = k >> 1, lane = k & 1;
        {
            float4 A  = sh[bj0 + 2 * p];
            float4 Bv = sh[bj0 + 2 * p + 1];
            float cx = lane ? A.y  : A.x;
            float cy = lane ? A.w  : A.z;
            float cz = lane ? Bv.y : Bv.x;
            float cw = lane ? Bv.w : Bv.z;
            float cr = fmaf(cz, az0, fmaf(cy, ay0, __fmul_rn(cx, ax0)));
            float ek = fmaf(-2.0f, cr, __fadd_rn(sq0, cw));
            if (ek == best0) kw0 = k;   // descending k: smallest k survives
        }
        {
            float4 A  = sh[bj1 + 2 * p];
            float4 Bv = sh[bj1 + 2 * p + 1];
            float cx = lane ? A.y  : A.x;
            float cy = lane ? A.w  : A.z;
            float cz = lane ? Bv.y : Bv.x;
            float cw = lane ? Bv.w : Bv.z;
            float cr = fmaf(cz, az1, fmaf(cy, ay1, __fmul_rn(cx, ax1)));
            float ek = fmaf(-2.0f, cr, __fadd_rn(sq1, cw));
            if (ek == best1) kw1 = k;
        }
    }

    red[0][threadIdx.x] = make_float2(best0, (float)(bj0 + kw0));
    red[1][threadIdx.x] = make_float2(best1, (float)(bj1 + kw1));
    __syncthreads();

    // ---- merge the 4 chunks; ascending chunk order, strict < keeps the
    //      earliest chunk (smaller candidate index) on exact ties ----------
    if (threadIdx.x < 256) {
        const int l  = threadIdx.x;        // query lane 0..255
        const int qi = l * gridDim.x + blockIdx.x;
        if (qi < Nq) {
            const int ql = l & 1;          // which query of the pair
            const int qp = l >> 1;         // query pair
            float2 r = red[ql][qp];        // chunk 0
#pragma unroll
            for (int cth = 1; cth < NCHUNK; cth++) {
                float2 rc = red[ql][cth * 128 + qp];
                if (rc.x < r.x) r = rc;
            }
            dist_out[(size_t)b * Nq + qi] = r.x;
            idx_out [(size_t)b * Nq + qi] = r.y;
        }
    }
}

extern "C" void kernel_launch(void* const* d_in, const int* in_sizes, int n_in,
                              void* d_out, int out_size) {
    const float* xyz1 = (const float*)d_in[0];
    const float* xyz2 = (const float*)d_in[1];
    float* out = (float*)d_out;

    const int B = 2;
    const int N = in_sizes[0] / (3 * B);
    const int M = in_sizes[1] / (3 * B);
    const int maxNM = (N > M) ? N : M;

    const size_t shmem = (size_t)maxNM * sizeof(float4);  // 128 KB for 8192
    cudaFuncSetAttribute(chamfer_kernel,
                         cudaFuncAttributeMaxDynamicSharedMemorySize,
                         (int)shmem);

    // 37 * 2 * 2 = 148 CTAs: one per SM, queries interleaved for balance.
    dim3 grid(37, B, 2);
    chamfer_kernel<<<grid, THREADS, shmem>>>(xyz1, xyz2, out, N, M, B);
}